// round 16
// baseline (speedup 1.0000x reference)
#include <cuda_runtime.h>

// Shapes (fixed): O=256, I=512, K=3, C=128, B=128
// Inputs (metadata order):
//   d_in[0] x                (B=128, I=512)  f32
//   d_in[1] control_points   (O=256, 4)      f32 (unused; k=3 fixed)
//   d_in[2] control_values   (O=256, 4, C=128) f32
//   d_in[3] expansion_matrix (C=128, I=512)  f32
// Output: (O=256, B=128, T=512) f32
//
//   Y[c,b]    = sum_f E[c,f] x[b,f]                 (K1)
//   Zp[h][o,b]= sum_{c in half h} cv[o,k,c] Y[c,b]  (K2, split-c partials)
//   out[o,b,t]= piecewise-linear in t from Z        (K3, pure store stream)

static constexpr int C_ = 128;
static constexpr int B_ = 128;
static constexpr int O_ = 256;

// Scratch (static device globals — no allocation)
__device__ float  g_Y[C_ * B_];           // Y[c][b]  (b contiguous, c-major)
__device__ float4 g_Zp[2][O_ * B_];       // partial Z over c-halves

// ---------------------------------------------------------------------------
// K1: warp-per-output Y[c][b] = dot(E[c,:], x[b,:]).
// Lane l reads float4 elements l, l+32, l+64, l+96 (coalesced), shuffle-reduce.
// Block = 512 threads = 16 warps = 4c x 4b tile; grid (32, 32).
// ---------------------------------------------------------------------------
__global__ void __launch_bounds__(512)
y_gemm_kernel(const float* __restrict__ x, const float* __restrict__ E) {
    const int w    = threadIdx.x >> 5;
    const int lane = threadIdx.x & 31;
    const int c = blockIdx.x * 4 + (w >> 2);
    const int b = blockIdx.y * 4 + (w & 3);

    const float4* __restrict__ E4 = (const float4*)E + c * 128 + lane;
    const float4* __restrict__ x4 = (const float4*)x + b * 128 + lane;

    const float4 e0 = E4[0],  xv0 = x4[0];
    const float4 e1 = E4[32], xv1 = x4[32];
    const float4 e2 = E4[64], xv2 = x4[64];
    const float4 e3 = E4[96], xv3 = x4[96];

    float4 a0, a1;
    a0.x = e0.x * xv0.x; a0.y = e0.y * xv0.y; a0.z = e0.z * xv0.z; a0.w = e0.w * xv0.w;
    a1.x = e1.x * xv1.x; a1.y = e1.y * xv1.y; a1.z = e1.z * xv1.z; a1.w = e1.w * xv1.w;
    a0.x = fmaf(e2.x, xv2.x, a0.x); a0.y = fmaf(e2.y, xv2.y, a0.y);
    a0.z = fmaf(e2.z, xv2.z, a0.z); a0.w = fmaf(e2.w, xv2.w, a0.w);
    a1.x = fmaf(e3.x, xv3.x, a1.x); a1.y = fmaf(e3.y, xv3.y, a1.y);
    a1.z = fmaf(e3.z, xv3.z, a1.z); a1.w = fmaf(e3.w, xv3.w, a1.w);

    float s = ((a0.x + a1.x) + (a0.y + a1.y)) + ((a0.z + a1.z) + (a0.w + a1.w));
#pragma unroll
    for (int off = 16; off > 0; off >>= 1)
        s += __shfl_down_sync(0xFFFFFFFFu, s, off);
    if (lane == 0) g_Y[c * B_ + b] = s;     // c-major for K2 coalescing
}

// ---------------------------------------------------------------------------
// K2: partial Z.  grid 512 = (o, c-half), block 128 (b).
// Each thread accumulates 64 c's for all 4 k's; Y reads coalesced (b contig),
// cv broadcast from shared.  Two partial buffers -> no atomics, no zeroing.
// ---------------------------------------------------------------------------
__global__ void __launch_bounds__(128)
z_kernel(const float* __restrict__ cv) {
    __shared__ float scv[512];
    const int o    = blockIdx.x >> 1;
    const int half = blockIdx.x & 1;
    const int b    = threadIdx.x;

    ((float4*)scv)[b] = ((const float4*)(cv + (size_t)o * 512))[b];
    __syncthreads();

    const float* __restrict__ Yb  = g_Y + half * 64 * B_ + b;
    const float* __restrict__ cvh = scv + half * 64;

    float a0 = 0.f, a1 = 0.f, a2 = 0.f, a3 = 0.f;
#pragma unroll 8
    for (int c = 0; c < 64; ++c) {
        const float y = Yb[c * B_];
        a0 = fmaf(cvh[c],       y, a0);
        a1 = fmaf(cvh[128 + c], y, a1);
        a2 = fmaf(cvh[256 + c], y, a2);
        a3 = fmaf(cvh[384 + c], y, a3);
    }
    g_Zp[half][o * B_ + b] = make_float4(a0, a1, a2, a3);
}

// ---------------------------------------------------------------------------
// K3: pure piecewise-linear store stream.  One warp per (o,b) row; lane owns
// 16 consecutive t.  v(t) = (z_j - j*dz_j) + t*(h*dz_j) per segment; a lane's
// span crosses a knot at most once -> two affine running sums + per-lane
// switch select.  No smem, no barrier, no shuffle.  4 x STG.128 (streaming).
// grid 4096 x 256 (8 rows/block).
// ---------------------------------------------------------------------------
__global__ void __launch_bounds__(256)
spline_write_kernel(float* __restrict__ out) {
    const int rid  = blockIdx.x * 8 + (threadIdx.x >> 5);
    const int lane = threadIdx.x & 31;

    const float4 za = g_Zp[0][rid];          // broadcast (same addr all lanes)
    const float4 zb = g_Zp[1][rid];
    const float z0 = za.x + zb.x;
    const float z1 = za.y + zb.y;
    const float z2 = za.z + zb.z;
    const float z3 = za.w + zb.w;

    const float dz0 = z1 - z0;
    const float dz1 = z2 - z1;
    const float dz2 = z3 - z2;
    const float h = 3.0f / 511.0f;

    const int t0  = lane << 4;
    const int t15 = t0 + 15;
    const int jlo = (t0  >= 341) ? 2 : ((t0  >= 171) ? 1 : 0);
    const int jhi = (t15 >= 341) ? 2 : ((t15 >= 171) ? 1 : 0);

    const float s_lo = h * ((jlo == 0) ? dz0 : ((jlo == 1) ? dz1 : dz2));
    const float b_lo = (jlo == 0) ? z0 : ((jlo == 1) ? (z1 - dz1) : (z2 - 2.0f * dz2));
    const float s_hi = h * ((jhi == 0) ? dz0 : ((jhi == 1) ? dz1 : dz2));
    const float b_hi = (jhi == 0) ? z0 : ((jhi == 1) ? (z1 - dz1) : (z2 - 2.0f * dz2));

    const int swl = (jlo == jhi) ? 64 : (((jhi == 1) ? 171 : 341) - t0);

    const float tf = (float)t0;
    float vlo = fmaf(tf, s_lo, b_lo);
    float vhi = fmaf(tf, s_hi, b_hi);

    float4* __restrict__ op = (float4*)(out + (size_t)rid * 512 + t0);
#pragma unroll
    for (int q = 0; q < 4; ++q) {
        float4 r;
        r.x = ((q * 4 + 0) >= swl) ? vhi : vlo;  vlo += s_lo;  vhi += s_hi;
        r.y = ((q * 4 + 1) >= swl) ? vhi : vlo;  vlo += s_lo;  vhi += s_hi;
        r.z = ((q * 4 + 2) >= swl) ? vhi : vlo;  vlo += s_lo;  vhi += s_hi;
        r.w = ((q * 4 + 3) >= swl) ? vhi : vlo;  vlo += s_lo;  vhi += s_hi;
        __stcs(op + q, r);                   // write-once: evict-first
    }
}

// ---------------------------------------------------------------------------
extern "C" void kernel_launch(void* const* d_in, const int* in_sizes, int n_in,
                              void* d_out, int out_size) {
    const float* x  = (const float*)d_in[0];
    const float* cv = (const float*)d_in[2];
    const float* E  = (const float*)d_in[3];
    float* out = (float*)d_out;

    y_gemm_kernel<<<dim3(32, 32), 512>>>(x, E);
    z_kernel<<<2 * O_, 128>>>(cv);
    spline_write_kernel<<<(O_ * B_) / 8, 256>>>(out);
}